// round 9
// baseline (speedup 1.0000x reference)
#include <cuda_runtime.h>
#include <math.h>

#define SLEN 1024
#define NM   32
#define HID  128
#define NB   1024

typedef unsigned long long u64;

// ---------------- scratch (static device memory; no allocation) ----------------
__device__ float g_tabC[SLEN*NM];          // cos(2*pi*m*s/S), [s][m]
__device__ float g_tabS[SLEN*NM];          // sin(2*pi*m*s/S), [s][m]
__device__ float g_w1tr[NM*HID];           // [m][ch]
__device__ float g_w1ti[NM*HID];
__device__ float g_w2tr[NM*HID*HID];       // [m][i][o]
__device__ float g_w2ti[NM*HID*HID];
__device__ float g_Zf [2*NM*NB*HID];       // [(m*2+ri)][b][ch]
__device__ float g_of2[2*NM*NB*HID];       // [(m*2+ri)][b][o]

// ---------------- packed f32x2 helpers ----------------
__device__ __forceinline__ u64 pk2(float lo, float hi) {
    u64 r; asm("mov.b64 %0, {%1, %2};" : "=l"(r) : "f"(lo), "f"(hi)); return r;
}
__device__ __forceinline__ void un2(u64 v, float& lo, float& hi) {
    asm("mov.b64 {%0, %1}, %2;" : "=f"(lo), "=f"(hi) : "l"(v));
}
__device__ __forceinline__ u64 f2fma(u64 a, u64 b, u64 c) {
    u64 d; asm("fma.rn.f32x2 %0, %1, %2, %3;" : "=l"(d) : "l"(a), "l"(b), "l"(c)); return d;
}
__device__ __forceinline__ u64 f2mul(u64 a, u64 b) {
    u64 d; asm("mul.rn.f32x2 %0, %1, %2;" : "=l"(d) : "l"(a), "l"(b)); return d;
}
__device__ __forceinline__ u64 f2add(u64 a, u64 b) {
    u64 d; asm("add.rn.f32x2 %0, %1, %2;" : "=l"(d) : "l"(a), "l"(b)); return d;
}
__device__ __forceinline__ u64 f2sub(u64 a, u64 b) {       // a - b
    return f2fma(b, pk2(-1.0f, -1.0f), a);
}
__device__ __forceinline__ u64 shfl64(u64 v, int mask) {
    return __shfl_xor_sync(0xffffffffu, v, mask);
}
__device__ __forceinline__ u64 dal(double d) { return __double_as_longlong(d); }
#define PKC(x) pk2((x), (x))

// High-accuracy GELU (A&S 7.1.26 erf), used on special points only.
__device__ __forceinline__ float gelu_fast(float x) {
    float q    = fabsf(x) * 0.70710678118654752f;
    float t    = __fdividef(1.0f, fmaf(0.3275911f, q, 1.0f));
    float poly = fmaf(fmaf(fmaf(fmaf(1.061405429f, t, -1.453152027f),
                               t, 1.421413741f),
                          t, -0.284496736f),
                      t, 0.254829592f) * t;
    float er   = 1.0f - poly * __expf(-q * q);
    float phi  = fmaf(copysignf(er, x), 0.5f, 0.5f);
    return x * phi;
}

// Two-point GELU, hot path: A&S 7.1.25 3-term erf (abs err 2.5e-5), packed poly.
__device__ __forceinline__ void gelu2(float xa, float xb, float& za, float& zb) {
    float qa = fabsf(xa) * 0.70710678118654752f;
    float qb = fabsf(xb) * 0.70710678118654752f;
    float ta = __fdividef(1.0f, fmaf(0.47047f, qa, 1.0f));
    float tb = __fdividef(1.0f, fmaf(0.47047f, qb, 1.0f));
    u64 t2 = pk2(ta, tb);
    u64 p  = f2fma(t2, PKC(0.7478556f), PKC(-0.0958798f));
    p = f2fma(p, t2, PKC(0.3480242f));
    p = f2mul(p, t2);
    float ea = __expf(-qa * qa), eb = __expf(-qb * qb);
    float pa, pb; un2(p, pa, pb);
    float era = fmaf(-pa, ea, 1.0f), erb = fmaf(-pb, eb, 1.0f);
    za = xa * fmaf(copysignf(era, xa), 0.5f, 0.5f);
    zb = xb * fmaf(copysignf(erb, xb), 0.5f, 0.5f);
}

// ---------------- K_tab: exact trig tables ----------------
__global__ void k_tab() {
    int idx = blockIdx.x * blockDim.x + threadIdx.x;
    if (idx >= SLEN * NM) return;
    int s = idx >> 5, m = idx & 31;
    int k = (s * m) & (SLEN - 1);
    float x = (float)k * (1.0f / 512.0f);
    float sv, cv;
    sincospif(x, &sv, &cv);
    g_tabC[idx] = cv;
    g_tabS[idx] = sv;
}

// ---------------- K_w: weight transposes ----------------
__global__ void k_w(const float* __restrict__ w1r, const float* __restrict__ w1i,
                    const float* __restrict__ w2r, const float* __restrict__ w2i) {
    int tid = blockIdx.x * blockDim.x + threadIdx.x;
    if (tid < NM * HID) {
        int ch = tid >> 5, m = tid & 31;
        g_w1tr[m * HID + ch] = w1r[tid];
        g_w1ti[m * HID + ch] = w1i[tid];
    }
    if (tid < NM * HID * HID) {
        int m = tid & 31; int io = tid >> 5;
        int i = io >> 7;  int o = io & 127;
        g_w2tr[(m * HID + i) * HID + o] = w2r[tid];
        g_w2ti[(m * HID + i) * HID + o] = w2i[tid];
    }
}

// ---------------- K_layer1: 2 rows/block, 4 threads/channel, 8 modes/thread ------------
// Warp = 8 channels x 4 threads (q = lane&3 owns one point of each quad).
// Quad for p: s0=p (q0), s1=1024-p (q1), s2=512+p (q2), s3=512-p (q3).
// Y_q = (Ue + a_q*Uo) + b_q*(Ve + a_q*Vo), a=(+,+,-,-), b=(+,-,+,-).
__global__ __launch_bounds__(512, 1) void k_layer1(const float* __restrict__ hin) {
    __shared__ float h_sm[2][SLEN];
    __shared__ float red[2][64][4];
    __shared__ float Hf[2][64];                // [r][0:32) real, [32:64) imag
    int t = threadIdx.x;
    int b0 = blockIdx.x * 2, b1 = b0 + 1;

    // stage 2 rows of h
    {
        const float4* s0 = reinterpret_cast<const float4*>(hin + (size_t)b0 * SLEN);
        const float4* s1 = reinterpret_cast<const float4*>(hin + (size_t)b1 * SLEN);
        float4* d0 = reinterpret_cast<float4*>(h_sm[0]);
        float4* d1 = reinterpret_cast<float4*>(h_sm[1]);
        for (int j = t; j < SLEN / 4; j += 512) { d0[j] = s0[j]; d1[j] = s1[j]; }
    }
    __syncthreads();

    // forward DFT (both rows): Hfr[m] = sum h*cos, Hfi[m] = -sum h*sin
    {
        int r = t >> 8, out = (t >> 2) & 63, seg = t & 3;
        int m = out & 31, isI = out >> 5;
        const float* tab = isI ? g_tabS : g_tabC;
        float acc = 0.0f;
        int s0 = seg * 256;
        #pragma unroll 8
        for (int j = 0; j < 256; j++) {
            int s = s0 + j;
            acc = fmaf(h_sm[r][s], __ldg(&tab[s * NM + m]), acc);
        }
        red[r][out][seg] = acc;
    }
    __syncthreads();
    if (t < 128) {
        int r = t >> 6, out = t & 63;
        float v = red[r][out][0] + red[r][out][1] + red[r][out][2] + red[r][out][3];
        Hf[r][out] = (out >= 32) ? -v : v;
    }
    __syncthreads();

    int w    = t >> 5;
    int lane = t & 31;
    int chan8 = lane >> 2;
    int q    = lane & 3;
    int ch   = w * 8 + chan8;
    float aq = (q < 2) ? 1.0f : -1.0f;         // alpha
    float bq = (q & 1) ? -1.0f : 1.0f;         // beta
    float s1sgn = -bq;                         // for z-diff butterfly

    // coefficients (8 modes per thread, per row)
    u64 ar2[2][4], ai2[2][4], zfr2[2][4], zfi2[2][4];
    #pragma unroll
    for (int r = 0; r < 2; r++) {
        #pragma unroll
        for (int j = 0; j < 4; j++) {
            float arj[2], aij[2];
            #pragma unroll
            for (int e = 0; e < 2; e++) {
                int m = 8 * q + 2 * j + e;
                float hr = Hf[r][m], hi = Hf[r][32 + m];
                float a1 = __ldg(&g_w1tr[m * HID + ch]);
                float b1 = __ldg(&g_w1ti[m * HID + ch]);
                float km = (m == 0) ? (1.0f / SLEN) : (2.0f / SLEN);
                arj[e] = km * (hr * a1 - hi * b1);
                float oi = km * (hr * b1 + hi * a1);
                aij[e] = (m == 0) ? 0.0f : -oi;
            }
            ar2[r][j] = pk2(arj[0], arj[1]);
            ai2[r][j] = pk2(aij[0], aij[1]);
            zfr2[r][j] = 0ull; zfi2[r][j] = 0ull;
        }
    }

    const double2* tC2 = reinterpret_cast<const double2*>(g_tabC);
    const double2* tS2 = reinterpret_cast<const double2*>(g_tabS);

    // ---- special points s=0, 512 (sin=0) ----
    {
        u64 c0[4], c5[4];
        #pragma unroll
        for (int jj = 0; jj < 2; jj++) {
            double2 a = __ldg(&tC2[0 * 8 + q * 2 + jj]);
            double2 c = __ldg(&tC2[512 * 8 + q * 2 + jj]);
            c0[2*jj] = dal(a.x); c0[2*jj+1] = dal(a.y);
            c5[2*jj] = dal(c.x); c5[2*jj+1] = dal(c.y);
        }
        #pragma unroll
        for (int r = 0; r < 2; r++) {
            u64 t0 = 0ull, t5 = 0ull;
            #pragma unroll
            for (int j = 0; j < 4; j++) {
                t0 = f2fma(ar2[r][j], c0[j], t0);
                t5 = f2fma(ar2[r][j], c5[j], t5);
            }
            t0 = f2add(t0, shfl64(t0, 1)); t0 = f2add(t0, shfl64(t0, 2));
            t5 = f2add(t5, shfl64(t5, 1)); t5 = f2add(t5, shfl64(t5, 2));
            float e, o;
            un2(t0, e, o); float z0 = gelu_fast(e + o);
            un2(t5, e, o); float z5 = gelu_fast(e + o);
            #pragma unroll
            for (int j = 0; j < 4; j++) {
                zfr2[r][j] = f2fma(PKC(z0), c0[j], zfr2[r][j]);
                zfr2[r][j] = f2fma(PKC(z5), c5[j], zfr2[r][j]);
            }
        }
    }
    // ---- special pair s=256 / s=768 ----
    {
        u64 c6[4], s6[4];
        #pragma unroll
        for (int jj = 0; jj < 2; jj++) {
            double2 a = __ldg(&tC2[256 * 8 + q * 2 + jj]);
            double2 s = __ldg(&tS2[256 * 8 + q * 2 + jj]);
            c6[2*jj] = dal(a.x); c6[2*jj+1] = dal(a.y);
            s6[2*jj] = dal(s.x); s6[2*jj+1] = dal(s.y);
        }
        #pragma unroll
        for (int r = 0; r < 2; r++) {
            u64 tu = 0ull, tv = 0ull;
            #pragma unroll
            for (int j = 0; j < 4; j++) {
                tu = f2fma(ar2[r][j], c6[j], tu);
                tv = f2fma(ai2[r][j], s6[j], tv);
            }
            tu = f2add(tu, shfl64(tu, 1)); tu = f2add(tu, shfl64(tu, 2));
            tv = f2add(tv, shfl64(tv, 1)); tv = f2add(tv, shfl64(tv, 2));
            float ue, uo, ve, vo;
            un2(tu, ue, uo); un2(tv, ve, vo);
            float U = ue + uo, V = ve + vo;
            float z256 = gelu_fast(U + V), z768 = gelu_fast(U - V);
            #pragma unroll
            for (int j = 0; j < 4; j++) {
                zfr2[r][j] = f2fma(PKC(z256 + z768), c6[j], zfr2[r][j]);
                zfi2[r][j] = f2fma(PKC(z768 - z256), s6[j], zfi2[r][j]);
            }
        }
    }

    // ---- quad mainloop p = 1..255 ----
    for (int p = 1; p <= 255; p++) {
        u64 c2[4], s2[4];
        #pragma unroll
        for (int jj = 0; jj < 2; jj++) {
            double2 a = __ldg(&tC2[p * 8 + q * 2 + jj]);
            double2 s = __ldg(&tS2[p * 8 + q * 2 + jj]);
            c2[2*jj] = dal(a.x); c2[2*jj+1] = dal(a.y);
            s2[2*jj] = dal(s.x); s2[2*jj+1] = dal(s.y);
        }
        // synth partials per row
        u64 u2r0 = 0ull, v2r0 = 0ull, u2r1 = 0ull, v2r1 = 0ull;
        #pragma unroll
        for (int j = 0; j < 4; j++) {
            u2r0 = f2fma(ar2[0][j], c2[j], u2r0);
            v2r0 = f2fma(ai2[0][j], s2[j], v2r0);
            u2r1 = f2fma(ar2[1][j], c2[j], u2r1);
            v2r1 = f2fma(ai2[1][j], s2[j], v2r1);
        }
        // 4-lane sum reduction (both parities stay packed)
        u2r0 = f2add(u2r0, shfl64(u2r0, 1)); u2r0 = f2add(u2r0, shfl64(u2r0, 2));
        v2r0 = f2add(v2r0, shfl64(v2r0, 1)); v2r0 = f2add(v2r0, shfl64(v2r0, 2));
        u2r1 = f2add(u2r1, shfl64(u2r1, 1)); u2r1 = f2add(u2r1, shfl64(u2r1, 2));
        v2r1 = f2add(v2r1, shfl64(v2r1, 1)); v2r1 = f2add(v2r1, shfl64(v2r1, 2));
        float ue0, uo0, ve0, vo0, ue1, uo1, ve1, vo1;
        un2(u2r0, ue0, uo0); un2(v2r0, ve0, vo0);
        un2(u2r1, ue1, uo1); un2(v2r1, ve1, vo1);
        float Y0 = fmaf(bq, fmaf(aq, vo0, ve0), fmaf(aq, uo0, ue0));
        float Y1 = fmaf(bq, fmaf(aq, vo1, ve1), fmaf(aq, uo1, ue1));
        float z0, z1;
        gelu2(Y0, Y1, z0, z1);                 // rows packed through GELU

        // analysis weight butterflies (rows packed in each u64)
        u64 zz  = pk2(z0, z1);
        u64 zzO = shfl64(zz, 1);
        u64 a2 = f2add(zz, zzO);
        u64 d2 = f2mul(f2sub(zz, zzO), PKC(s1sgn));   // (z_odd - z_even) per pair
        u64 a2O = shfl64(a2, 2);
        u64 d2O = shfl64(d2, 2);
        u64 Rp2 = f2add(a2, a2O);
        u64 Rm2 = f2mul(f2sub(a2, a2O), PKC(aq));     // (z0+z1)-(z2+z3)
        u64 Ip2 = f2add(d2, d2O);
        u64 Im2 = f2mul(f2sub(d2, d2O), PKC(aq));
        float Rp0, Rp1, Rm0, Rm1, Ip0, Ip1, Im0, Im1;
        un2(Rp2, Rp0, Rp1); un2(Rm2, Rm0, Rm1);
        un2(Ip2, Ip0, Ip1); un2(Im2, Im0, Im1);
        u64 r2_0 = pk2(Rp0, Rm0), i2_0 = pk2(Ip0, Im0);
        u64 r2_1 = pk2(Rp1, Rm1), i2_1 = pk2(Ip1, Im1);
        #pragma unroll
        for (int j = 0; j < 4; j++) {
            zfr2[0][j] = f2fma(r2_0, c2[j], zfr2[0][j]);
            zfi2[0][j] = f2fma(i2_0, s2[j], zfi2[0][j]);
            zfr2[1][j] = f2fma(r2_1, c2[j], zfr2[1][j]);
            zfi2[1][j] = f2fma(i2_1, s2[j], zfi2[1][j]);
        }
    }

    // store Zf
    #pragma unroll
    for (int r = 0; r < 2; r++) {
        int b = b0 + r;
        #pragma unroll
        for (int j = 0; j < 4; j++) {
            float r0, r1, i0, i1;
            un2(zfr2[r][j], r0, r1);
            un2(zfi2[r][j], i0, i1);
            int m0 = 8 * q + 2 * j;
            g_Zf[((size_t)((m0    ) * 2 + 0) * NB + b) * HID + ch] = r0;
            g_Zf[((size_t)((m0    ) * 2 + 1) * NB + b) * HID + ch] = i0;
            g_Zf[((size_t)((m0 + 1) * 2 + 0) * NB + b) * HID + ch] = r1;
            g_Zf[((size_t)((m0 + 1) * 2 + 1) * NB + b) * HID + ch] = i1;
        }
    }
}

// ---------------- K_mix: per-mode complex GEMM (scalar, proven form) ----------------
__global__ __launch_bounds__(256, 2) void k_mix() {
    int m  = blockIdx.x;
    int bt = blockIdx.y;
    __shared__ float Zr[64 * 33], Zi[64 * 33];
    __shared__ float Wr[32 * 128], Wi[32 * 128];
    int t = threadIdx.x;
    int bo_g = t >> 4, o_g = t & 15;
    int b0 = bo_g * 4, o0 = o_g * 8;

    float accr[4][8], acci[4][8];
    #pragma unroll
    for (int x = 0; x < 4; x++)
        #pragma unroll
        for (int y = 0; y < 8; y++) { accr[x][y] = 0.0f; acci[x][y] = 0.0f; }

    const float* Zsr = g_Zf + ((size_t)(m * 2 + 0) * NB + bt * 64) * HID;
    const float* Zsi = g_Zf + ((size_t)(m * 2 + 1) * NB + bt * 64) * HID;

    for (int i0 = 0; i0 < HID; i0 += 32) {
        __syncthreads();
        for (int idx = t; idx < 64 * 32; idx += 256) {
            int bb = idx >> 5, ic = idx & 31;
            Zr[bb * 33 + ic] = Zsr[bb * HID + i0 + ic];
            Zi[bb * 33 + ic] = Zsi[bb * HID + i0 + ic];
        }
        for (int idx = t; idx < 32 * 128; idx += 256) {
            int ic = idx >> 7, o = idx & 127;
            Wr[idx] = g_w2tr[((size_t)m * HID + i0 + ic) * HID + o];
            Wi[idx] = g_w2ti[((size_t)m * HID + i0 + ic) * HID + o];
        }
        __syncthreads();
        #pragma unroll 4
        for (int ic = 0; ic < 32; ic++) {
            float zr[4], zi[4];
            #pragma unroll
            for (int bb = 0; bb < 4; bb++) {
                zr[bb] = Zr[(b0 + bb) * 33 + ic];
                zi[bb] = Zi[(b0 + bb) * 33 + ic];
            }
            float wr[8], wi[8];
            #pragma unroll
            for (int qq = 0; qq < 2; qq++) {
                float4 a = reinterpret_cast<const float4*>(&Wr[ic * 128 + o0])[qq];
                float4 c = reinterpret_cast<const float4*>(&Wi[ic * 128 + o0])[qq];
                wr[4*qq+0]=a.x; wr[4*qq+1]=a.y; wr[4*qq+2]=a.z; wr[4*qq+3]=a.w;
                wi[4*qq+0]=c.x; wi[4*qq+1]=c.y; wi[4*qq+2]=c.z; wi[4*qq+3]=c.w;
            }
            #pragma unroll
            for (int bb = 0; bb < 4; bb++)
                #pragma unroll
                for (int oo = 0; oo < 8; oo++) {
                    accr[bb][oo] = fmaf(zr[bb], wr[oo], fmaf(-zi[bb], wi[oo], accr[bb][oo]));
                    acci[bb][oo] = fmaf(zr[bb], wi[oo], fmaf( zi[bb], wr[oo], acci[bb][oo]));
                }
        }
    }
    #pragma unroll
    for (int bb = 0; bb < 4; bb++) {
        size_t rowr = ((size_t)(m * 2 + 0) * NB + bt * 64 + b0 + bb) * HID + o0;
        size_t rowi = ((size_t)(m * 2 + 1) * NB + bt * 64 + b0 + bb) * HID + o0;
        #pragma unroll
        for (int oo = 0; oo < 8; oo++) {
            g_of2[rowr + oo] = accr[bb][oo];
            g_of2[rowi + oo] = acci[bb][oo];
        }
    }
}

// ---------------- K_layer2: 2 rows/block, 4 threads/channel, synth+gelu+mean ----------
__global__ __launch_bounds__(512, 1) void k_layer2(float* __restrict__ out) {
    int t = threadIdx.x;
    int b0 = blockIdx.x * 2, b1 = b0 + 1;
    int w    = t >> 5;
    int lane = t & 31;
    int chan8 = lane >> 2;
    int q    = lane & 3;
    int o    = w * 8 + chan8;
    float aq = (q < 2) ? 1.0f : -1.0f;
    float bq = (q & 1) ? -1.0f : 1.0f;

    // coefficients (8 modes/thread, per row)
    u64 br2[2][4], bi2[2][4];
    #pragma unroll
    for (int r = 0; r < 2; r++) {
        int b = b0 + r;
        #pragma unroll
        for (int j = 0; j < 4; j++) {
            float brj[2], bij[2];
            #pragma unroll
            for (int e = 0; e < 2; e++) {
                int m = 8 * q + 2 * j + e;
                float orr = __ldg(&g_of2[((size_t)(m * 2 + 0) * NB + b) * HID + o]);
                float oii = __ldg(&g_of2[((size_t)(m * 2 + 1) * NB + b) * HID + o]);
                float km = (m == 0) ? (1.0f / SLEN) : (2.0f / SLEN);
                brj[e] = km * orr;
                bij[e] = (m == 0) ? 0.0f : -km * oii;
            }
            br2[r][j] = pk2(brj[0], brj[1]);
            bi2[r][j] = pk2(bij[0], bij[1]);
        }
    }

    const double2* tC2 = reinterpret_cast<const double2*>(g_tabC);
    const double2* tS2 = reinterpret_cast<const double2*>(g_tabS);
    float acc0 = 0.0f, acc1 = 0.0f;

    // ---- special points s=0, 512 ----
    {
        u64 c0[4], c5[4];
        #pragma unroll
        for (int jj = 0; jj < 2; jj++) {
            double2 a = __ldg(&tC2[0 * 8 + q * 2 + jj]);
            double2 c = __ldg(&tC2[512 * 8 + q * 2 + jj]);
            c0[2*jj] = dal(a.x); c0[2*jj+1] = dal(a.y);
            c5[2*jj] = dal(c.x); c5[2*jj+1] = dal(c.y);
        }
        #pragma unroll
        for (int r = 0; r < 2; r++) {
            u64 t0 = 0ull, t5 = 0ull;
            #pragma unroll
            for (int j = 0; j < 4; j++) {
                t0 = f2fma(br2[r][j], c0[j], t0);
                t5 = f2fma(br2[r][j], c5[j], t5);
            }
            t0 = f2add(t0, shfl64(t0, 1)); t0 = f2add(t0, shfl64(t0, 2));
            t5 = f2add(t5, shfl64(t5, 1)); t5 = f2add(t5, shfl64(t5, 2));
            float e, oo2;
            un2(t0, e, oo2); float z0 = gelu_fast(e + oo2);
            un2(t5, e, oo2); float z5 = gelu_fast(e + oo2);
            if (q == 0) { if (r == 0) acc0 += z0 + z5; else acc1 += z0 + z5; }
        }
    }
    // ---- special pair s=256 / 768 ----
    {
        u64 c6[4], s6[4];
        #pragma unroll
        for (int jj = 0; jj < 2; jj++) {
            double2 a = __ldg(&tC2[256 * 8 + q * 2 + jj]);
            double2 s = __ldg(&tS2[256 * 8 + q * 2 + jj]);
            c6[2*jj] = dal(a.x); c6[2*jj+1] = dal(a.y);
            s6[2*jj] = dal(s.x); s6[2*jj+1] = dal(s.y);
        }
        #pragma unroll
        for (int r = 0; r < 2; r++) {
            u64 tu = 0ull, tv = 0ull;
            #pragma unroll
            for (int j = 0; j < 4; j++) {
                tu = f2fma(br2[r][j], c6[j], tu);
                tv = f2fma(bi2[r][j], s6[j], tv);
            }
            tu = f2add(tu, shfl64(tu, 1)); tu = f2add(tu, shfl64(tu, 2));
            tv = f2add(tv, shfl64(tv, 1)); tv = f2add(tv, shfl64(tv, 2));
            float ue, uo, ve, vo;
            un2(tu, ue, uo); un2(tv, ve, vo);
            float U = ue + uo, V = ve + vo;
            float zsum = gelu_fast(U + V) + gelu_fast(U - V);
            if (q == 0) { if (r == 0) acc0 += zsum; else acc1 += zsum; }
        }
    }

    // ---- quad mainloop ----
    for (int p = 1; p <= 255; p++) {
        u64 c2[4], s2[4];
        #pragma unroll
        for (int jj = 0; jj < 2; jj++) {
            double2 a = __ldg(&tC2[p * 8 + q * 2 + jj]);
            double2 s = __ldg(&tS2[p * 8 + q * 2 + jj]);
            c2[2*jj] = dal(a.x); c2[2*jj+1] = dal(a.y);
            s2[2*jj] = dal(s.x); s2[2*jj+1] = dal(s.y);
        }
        u64 u2r0 = 0ull, v2r0 = 0ull, u2r1 = 0ull, v2r1 = 0ull;
        #pragma unroll
        for (int j = 0; j < 4; j++) {
            u2r0 = f2fma(br2[0][j], c2[j], u2r0);
            v2r0 = f2fma(bi2[0][j], s2[j], v2r0);
            u2r1 = f2fma(br2[1][j], c2[j], u2r1);
            v2r1 = f2fma(bi2[1][j], s2[j], v2r1);
        }
        u2r0 = f2add(u2r0, shfl64(u2r0, 1)); u2r0 = f2add(u2r0, shfl64(u2r0, 2));
        v2r0 = f2add(v2r0, shfl64(v2r0, 1)); v2r0 = f2add(v2r0, shfl64(v2r0, 2));
        u2r1 = f2add(u2r1, shfl64(u2r1, 1)); u2r1 = f2add(u2r1, shfl64(u2r1, 2));
        v2r1 = f2add(v2r1, shfl64(v2r1, 1)); v2r1 = f2add(v2r1, shfl64(v2r1, 2));
        float ue0, uo0, ve0, vo0, ue1, uo1, ve1, vo1;
        un2(u2r0, ue0, uo0); un2(v2r0, ve0, vo0);
        un2(u2r1, ue1, uo1); un2(v2r1, ve1, vo1);
        float Y0 = fmaf(bq, fmaf(aq, vo0, ve0), fmaf(aq, uo0, ue0));
        float Y1 = fmaf(bq, fmaf(aq, vo1, ve1), fmaf(aq, uo1, ue1));
        float z0, z1;
        gelu2(Y0, Y1, z0, z1);
        acc0 += z0;
        acc1 += z1;
    }

    // reduce the 4 point-owners and write
    u64 aa = pk2(acc0, acc1);
    aa = f2add(aa, shfl64(aa, 1));
    aa = f2add(aa, shfl64(aa, 2));
    if (q == 0) {
        float a0, a1;
        un2(aa, a0, a1);
        out[(size_t)b0 * HID + o] = a0 * (1.0f / SLEN);
        out[(size_t)b1 * HID + o] = a1 * (1.0f / SLEN);
    }
}

// ---------------- launch ----------------
extern "C" void kernel_launch(void* const* d_in, const int* in_sizes, int n_in,
                              void* d_out, int out_size) {
    const float* hin = nullptr;
    const float* w1p[2] = {nullptr, nullptr};
    const float* w2p[2] = {nullptr, nullptr};
    int n1 = 0, n2 = 0;
    for (int i = 0; i < n_in; i++) {
        int sz = in_sizes[i];
        const float* p = (const float*)d_in[i];
        if (sz == NB * SLEN) hin = p;
        else if (sz == HID * NM) { if (n1 < 2) w1p[n1++] = p; }
        else if (sz == HID * HID * NM) { if (n2 < 2) w2p[n2++] = p; }
    }
    float* out = (float*)d_out;

    k_tab<<<(SLEN * NM + 255) / 256, 256>>>();
    k_w<<<(NM * HID * HID + 255) / 256, 256>>>(w1p[0], w1p[1], w2p[0], w2p[1]);
    k_layer1<<<512, 512>>>(hin);
    dim3 g3(NM, 16);
    k_mix<<<g3, 256>>>();
    k_layer2<<<512, 512>>>(out);
}

// round 10
// speedup vs baseline: 1.5118x; 1.5118x over previous
#include <cuda_runtime.h>
#include <math.h>

#define SLEN 1024
#define NM   32
#define HID  128
#define NB   1024

typedef unsigned long long u64;

// ---------------- scratch (static device memory; no allocation) ----------------
__device__ float g_tabC[SLEN*NM];          // cos(2*pi*m*s/S), [s][m]
__device__ float g_tabS[SLEN*NM];          // sin(2*pi*m*s/S), [s][m]
__device__ float g_w1tr[NM*HID];           // [m][ch]
__device__ float g_w1ti[NM*HID];
__device__ float g_w2tr[NM*HID*HID];       // [m][i][o]
__device__ float g_w2ti[NM*HID*HID];
__device__ float g_Zf [2*NM*NB*HID];       // [(m*2+ri)][b][ch]
__device__ float g_of2[2*NM*NB*HID];       // [(m*2+ri)][b][o]

// ---------------- packed f32x2 helpers ----------------
__device__ __forceinline__ u64 pk2(float lo, float hi) {
    u64 r; asm("mov.b64 %0, {%1, %2};" : "=l"(r) : "f"(lo), "f"(hi)); return r;
}
__device__ __forceinline__ void un2(u64 v, float& lo, float& hi) {
    asm("mov.b64 {%0, %1}, %2;" : "=f"(lo), "=f"(hi) : "l"(v));
}
__device__ __forceinline__ u64 f2fma(u64 a, u64 b, u64 c) {
    u64 d; asm("fma.rn.f32x2 %0, %1, %2, %3;" : "=l"(d) : "l"(a), "l"(b), "l"(c)); return d;
}
__device__ __forceinline__ u64 f2mul(u64 a, u64 b) {
    u64 d; asm("mul.rn.f32x2 %0, %1, %2;" : "=l"(d) : "l"(a), "l"(b)); return d;
}
__device__ __forceinline__ u64 f2add(u64 a, u64 b) {
    u64 d; asm("add.rn.f32x2 %0, %1, %2;" : "=l"(d) : "l"(a), "l"(b)); return d;
}
__device__ __forceinline__ u64 dal(double d) { return __double_as_longlong(d); }
__device__ __forceinline__ unsigned s2u(const void* p) {
    return (unsigned)__cvta_generic_to_shared(p);
}
// 16B shared load -> two packed f32x2 operands
__device__ __forceinline__ void lds2u64(u64& a, u64& b, unsigned addr) {
    asm volatile("ld.shared.v2.u64 {%0, %1}, [%2];" : "=l"(a), "=l"(b) : "r"(addr));
}
#define PKC(x) pk2((x), (x))

// High-accuracy GELU (A&S 7.1.26 erf), used on special points only.
__device__ __forceinline__ float gelu_fast(float x) {
    float q    = fabsf(x) * 0.70710678118654752f;
    float t    = __fdividef(1.0f, fmaf(0.3275911f, q, 1.0f));
    float poly = fmaf(fmaf(fmaf(fmaf(1.061405429f, t, -1.453152027f),
                               t, 1.421413741f),
                          t, -0.284496736f),
                      t, 0.254829592f) * t;
    float er   = 1.0f - poly * __expf(-q * q);
    float phi  = fmaf(copysignf(er, x), 0.5f, 0.5f);
    return x * phi;
}

// Two-point GELU, hot path: A&S 7.1.25 3-term erf (abs err 2.5e-5), packed poly.
__device__ __forceinline__ void gelu2(float xa, float xb, float& za, float& zb) {
    float qa = fabsf(xa) * 0.70710678118654752f;
    float qb = fabsf(xb) * 0.70710678118654752f;
    float ta = __fdividef(1.0f, fmaf(0.47047f, qa, 1.0f));
    float tb = __fdividef(1.0f, fmaf(0.47047f, qb, 1.0f));
    u64 t2 = pk2(ta, tb);
    u64 p  = f2fma(t2, PKC(0.7478556f), PKC(-0.0958798f));
    p = f2fma(p, t2, PKC(0.3480242f));
    p = f2mul(p, t2);
    float ea = __expf(-qa * qa), eb = __expf(-qb * qb);
    float pa, pb; un2(p, pa, pb);
    float era = fmaf(-pa, ea, 1.0f), erb = fmaf(-pb, eb, 1.0f);
    za = xa * fmaf(copysignf(era, xa), 0.5f, 0.5f);
    zb = xb * fmaf(copysignf(erb, xb), 0.5f, 0.5f);
}

// ---------------- K_tab: exact trig tables ----------------
__global__ void k_tab() {
    int idx = blockIdx.x * blockDim.x + threadIdx.x;
    if (idx >= SLEN * NM) return;
    int s = idx >> 5, m = idx & 31;
    int k = (s * m) & (SLEN - 1);
    float x = (float)k * (1.0f / 512.0f);
    float sv, cv;
    sincospif(x, &sv, &cv);
    g_tabC[idx] = cv;
    g_tabS[idx] = sv;
}

// ---------------- K_w: weight transposes ----------------
__global__ void k_w(const float* __restrict__ w1r, const float* __restrict__ w1i,
                    const float* __restrict__ w2r, const float* __restrict__ w2i) {
    int tid = blockIdx.x * blockDim.x + threadIdx.x;
    if (tid < NM * HID) {
        int ch = tid >> 5, m = tid & 31;
        g_w1tr[m * HID + ch] = w1r[tid];
        g_w1ti[m * HID + ch] = w1i[tid];
    }
    if (tid < NM * HID * HID) {
        int m = tid & 31; int io = tid >> 5;
        int i = io >> 7;  int o = io & 127;
        g_w2tr[(m * HID + i) * HID + o] = w2r[tid];
        g_w2ti[(m * HID + i) * HID + o] = w2i[tid];
    }
}

// ---------------- K_layer1: DFT(h) -> mix w1 -> synth+gelu+analyze (smem tables) -------
// Block = one batch row b. 256 threads.
// Warp w handles channels [16w, 16w+16); lane>>4 selects mode-half (16 modes each).
__global__ __launch_bounds__(256, 2) void k_layer1(const float* __restrict__ hin) {
    __shared__ float h_sm[SLEN];
    __shared__ float red[64 * 4];
    __shared__ float Hf[64];                   // [0:32) real, [32:64) imag
    __shared__ __align__(16) float smC[64 * 32];   // 64-row chunk of cos table
    __shared__ __align__(16) float smS[64 * 32];   // 64-row chunk of sin table
    int b = blockIdx.x;
    int t = threadIdx.x;

    // stage h row
    {
        const float4* src = reinterpret_cast<const float4*>(hin + (size_t)b * SLEN);
        float4* dst = reinterpret_cast<float4*>(h_sm);
        for (int j = t; j < SLEN / 4; j += 256) dst[j] = src[j];
    }
    __syncthreads();

    // forward DFT of h: Hfr[m] = sum h*cos, Hfi[m] = -sum h*sin
    {
        int out = t & 63, seg = t >> 6;
        int m = out & 31; int isI = out >> 5;
        const float* tab = isI ? g_tabS : g_tabC;
        float acc = 0.0f;
        int s0 = seg * 256;
        #pragma unroll 8
        for (int j = 0; j < 256; j++) {
            int s = s0 + j;
            acc = fmaf(h_sm[s], __ldg(&tab[s * NM + m]), acc);
        }
        red[out * 4 + seg] = acc;
    }
    __syncthreads();
    if (t < 64) {
        float v = red[t * 4] + red[t * 4 + 1] + red[t * 4 + 2] + red[t * 4 + 3];
        Hf[t] = (t >= 32) ? -v : v;
    }
    __syncthreads();

    int lane = t & 31;
    int w    = t >> 5;
    int hh   = lane >> 4;                      // mode-half / point-group owner
    int ch   = w * 16 + (lane & 15);
    float sgn  = hh ? -1.0f : 1.0f;
    float msgn = -sgn;

    // synthesis coefficients: y(s) = sum ar[m]*cos + ai[m]*sin
    float ar[16], ai[16], zfr[16], zfi[16];
    #pragma unroll
    for (int j = 0; j < 16; j++) {
        int m = hh * 16 + j;
        float hr = Hf[m], hi = Hf[32 + m];
        float a1 = __ldg(&g_w1tr[m * HID + ch]);
        float b1 = __ldg(&g_w1ti[m * HID + ch]);
        float km = (m == 0) ? (1.0f / SLEN) : (2.0f / SLEN);
        ar[j] = km * (hr * a1 - hi * b1);
        float oi = km * (hr * b1 + hi * a1);
        ai[j] = (m == 0) ? 0.0f : -oi;         // DC imag dropped by irfft
        zfr[j] = 0.0f; zfi[j] = 0.0f;
    }

    const float4* tC = reinterpret_cast<const float4*>(g_tabC);
    const float4* tS = reinterpret_cast<const float4*>(g_tabS);
    int base = hh * 4;                         // float4 offset inside 8-float4 row

    // special points s=0 and s=512 (sin == 0 there)
    {
        float c0[16], c5[16];
        #pragma unroll
        for (int q = 0; q < 4; q++) {
            float4 a = __ldg(&tC[0 * 8 + base + q]);
            float4 c = __ldg(&tC[512 * 8 + base + q]);
            c0[4*q+0]=a.x; c0[4*q+1]=a.y; c0[4*q+2]=a.z; c0[4*q+3]=a.w;
            c5[4*q+0]=c.x; c5[4*q+1]=c.y; c5[4*q+2]=c.z; c5[4*q+3]=c.w;
        }
        float u0 = 0.0f, u5 = 0.0f;
        #pragma unroll
        for (int j = 0; j < 16; j++) {
            u0 = fmaf(ar[j], c0[j], u0);
            u5 = fmaf(ar[j], c5[j], u5);
        }
        u0 += __shfl_xor_sync(0xffffffffu, u0, 16);
        u5 += __shfl_xor_sync(0xffffffffu, u5, 16);
        float z0 = gelu_fast(u0), z5 = gelu_fast(u5);
        #pragma unroll
        for (int j = 0; j < 16; j++)
            zfr[j] = fmaf(z0, c0[j], fmaf(z5, c5[j], zfr[j]));
    }

    // special pair s=256 / s=768 (half-wave symmetry)
    {
        float c[16], sn[16];
        #pragma unroll
        for (int q = 0; q < 4; q++) {
            float4 a = __ldg(&tC[256 * 8 + base + q]);
            float4 s = __ldg(&tS[256 * 8 + base + q]);
            c [4*q+0]=a.x; c [4*q+1]=a.y; c [4*q+2]=a.z; c [4*q+3]=a.w;
            sn[4*q+0]=s.x; sn[4*q+1]=s.y; sn[4*q+2]=s.z; sn[4*q+3]=s.w;
        }
        float u = 0.0f, v = 0.0f;
        #pragma unroll
        for (int j = 0; j < 16; j++) {
            u = fmaf(ar[j], c[j], u);
            v = fmaf(ai[j], sn[j], v);
        }
        float ya = u + v, yb = u - v;          // y(256), y(768)
        ya += __shfl_xor_sync(0xffffffffu, ya, 16);
        yb += __shfl_xor_sync(0xffffffffu, yb, 16);
        float ymine = hh ? yb : ya;
        float zmine = gelu_fast(ymine);
        float zoth  = __shfl_xor_sync(0xffffffffu, zmine, 16);
        float z0 = hh ? zoth : zmine;          // z(256)
        float z1 = hh ? zmine : zoth;          // z(768)
        float zp = z0 + z1, zd = z1 - z0;
        #pragma unroll
        for (int j = 0; j < 16; j++) {
            zfr[j] = fmaf(zp, c[j],  zfr[j]);
            zfi[j] = fmaf(zd, sn[j], zfi[j]);
        }
    }

    // pack coefficients and accumulators into f32x2 pairs (even/odd mode lanes)
    u64 ar2[8], ai2[8], zfr2[8], zfi2[8];
    #pragma unroll
    for (int k = 0; k < 8; k++) {
        ar2[k]  = pk2(ar[2*k],  ar[2*k+1]);
        ai2[k]  = pk2(ai[2*k],  ai[2*k+1]);
        zfr2[k] = pk2(zfr[2*k], zfr[2*k+1]);
        zfi2[k] = pk2(zfi[2*k], zfi[2*k+1]);
    }

    unsigned smC_a = s2u(smC) + hh * 64;       // hh selects 16-float half of row
    unsigned smS_a = s2u(smS) + hh * 64;

    // quad points {p, 1024-p, 512+p, 512-p}, p = 1..255, smem-staged tables
    for (int pb = 0; pb < 256; pb += 64) {
        __syncthreads();
        // cooperative stage: rows pb..pb+63 of both tables (512 float4 each)
        for (int j = t; j < 512; j += 256) {
            int row = j >> 3, col = j & 7;
            reinterpret_cast<float4*>(smC)[j] = __ldg(&tC[(pb + row) * 8 + col]);
            reinterpret_cast<float4*>(smS)[j] = __ldg(&tS[(pb + row) * 8 + col]);
        }
        __syncthreads();
        int p0 = (pb == 0) ? 1 : pb;
        for (int p = p0; p < pb + 64; p++) {
            unsigned off = (unsigned)(p - pb) * 128;   // 32 floats/row
            u64 c2[8], s2[8];
            lds2u64(c2[0], c2[1], smC_a + off);
            lds2u64(c2[2], c2[3], smC_a + off + 16);
            lds2u64(c2[4], c2[5], smC_a + off + 32);
            lds2u64(c2[6], c2[7], smC_a + off + 48);
            lds2u64(s2[0], s2[1], smS_a + off);
            lds2u64(s2[2], s2[3], smS_a + off + 16);
            lds2u64(s2[4], s2[5], smS_a + off + 32);
            lds2u64(s2[6], s2[7], smS_a + off + 48);

            // split accumulation chains (2x4 deep) for latency
            u64 u2a = 0ull, u2b = 0ull, v2a = 0ull, v2b = 0ull;
            #pragma unroll
            for (int k = 0; k < 4; k++) {
                u2a = f2fma(ar2[k],     c2[k],     u2a);
                u2b = f2fma(ar2[k + 4], c2[k + 4], u2b);
                v2a = f2fma(ai2[k],     s2[k],     v2a);
                v2b = f2fma(ai2[k + 4], s2[k + 4], v2b);
            }
            float ue, uo, ve, vo;
            un2(f2add(u2a, u2b), ue, uo);
            un2(f2add(v2a, v2b), ve, vo);
            // select-free parity folds: keep = my points' combo, send = partner's
            float keepU = fmaf(sgn,  uo, ue);
            float sendU = fmaf(msgn, uo, ue);
            float keepV = fmaf(sgn,  vo, ve);
            float sendV = fmaf(msgn, vo, ve);
            float U = keepU + __shfl_xor_sync(0xffffffffu, sendU, 16);
            float V = keepV + __shfl_xor_sync(0xffffffffu, sendV, 16);
            float za, zb;
            gelu2(U + V, U - V, za, zb);       // t0: z(p), z(1024-p); t1: z(512+p), z(512-p)
            float sP = za + zb;                // pair-sum (cos side)
            float sM = zb - za;                // pair-diff (sin side)
            float oP = __shfl_xor_sync(0xffffffffu, sP, 16);
            float oM = __shfl_xor_sync(0xffffffffu, sM, 16);
            // cos weights: even = sP+oP, odd = sgn*(sP-oP); sin likewise
            u64 r2 = pk2(sP + oP, sgn * (sP - oP));
            u64 i2 = pk2(sM + oM, sgn * (sM - oM));
            #pragma unroll
            for (int k = 0; k < 8; k++) {
                zfr2[k] = f2fma(r2, c2[k], zfr2[k]);
                zfi2[k] = f2fma(i2, s2[k], zfi2[k]);
            }
        }
    }

    #pragma unroll
    for (int k = 0; k < 8; k++) {
        float r0, r1, i0, i1;
        un2(zfr2[k], r0, r1);
        un2(zfi2[k], i0, i1);
        int m0 = hh * 16 + 2 * k;
        g_Zf[((size_t)((m0    ) * 2 + 0) * NB + b) * HID + ch] = r0;
        g_Zf[((size_t)((m0    ) * 2 + 1) * NB + b) * HID + ch] = i0;
        g_Zf[((size_t)((m0 + 1) * 2 + 0) * NB + b) * HID + ch] = r1;
        g_Zf[((size_t)((m0 + 1) * 2 + 1) * NB + b) * HID + ch] = i1;
    }
}

// ---------------- K_mix: per-mode complex GEMM (scalar, proven form) ----------------
__global__ __launch_bounds__(256, 2) void k_mix() {
    int m  = blockIdx.x;
    int bt = blockIdx.y;
    __shared__ float Zr[64 * 33], Zi[64 * 33];
    __shared__ float Wr[32 * 128], Wi[32 * 128];
    int t = threadIdx.x;
    int bo_g = t >> 4, o_g = t & 15;
    int b0 = bo_g * 4, o0 = o_g * 8;

    float accr[4][8], acci[4][8];
    #pragma unroll
    for (int x = 0; x < 4; x++)
        #pragma unroll
        for (int y = 0; y < 8; y++) { accr[x][y] = 0.0f; acci[x][y] = 0.0f; }

    const float* Zsr = g_Zf + ((size_t)(m * 2 + 0) * NB + bt * 64) * HID;
    const float* Zsi = g_Zf + ((size_t)(m * 2 + 1) * NB + bt * 64) * HID;

    for (int i0 = 0; i0 < HID; i0 += 32) {
        __syncthreads();
        for (int idx = t; idx < 64 * 32; idx += 256) {
            int bb = idx >> 5, ic = idx & 31;
            Zr[bb * 33 + ic] = Zsr[bb * HID + i0 + ic];
            Zi[bb * 33 + ic] = Zsi[bb * HID + i0 + ic];
        }
        for (int idx = t; idx < 32 * 128; idx += 256) {
            int ic = idx >> 7, o = idx & 127;
            Wr[idx] = g_w2tr[((size_t)m * HID + i0 + ic) * HID + o];
            Wi[idx] = g_w2ti[((size_t)m * HID + i0 + ic) * HID + o];
        }
        __syncthreads();
        #pragma unroll 4
        for (int ic = 0; ic < 32; ic++) {
            float zr[4], zi[4];
            #pragma unroll
            for (int bb = 0; bb < 4; bb++) {
                zr[bb] = Zr[(b0 + bb) * 33 + ic];
                zi[bb] = Zi[(b0 + bb) * 33 + ic];
            }
            float wr[8], wi[8];
            #pragma unroll
            for (int q = 0; q < 2; q++) {
                float4 a = reinterpret_cast<const float4*>(&Wr[ic * 128 + o0])[q];
                float4 c = reinterpret_cast<const float4*>(&Wi[ic * 128 + o0])[q];
                wr[4*q+0]=a.x; wr[4*q+1]=a.y; wr[4*q+2]=a.z; wr[4*q+3]=a.w;
                wi[4*q+0]=c.x; wi[4*q+1]=c.y; wi[4*q+2]=c.z; wi[4*q+3]=c.w;
            }
            #pragma unroll
            for (int bb = 0; bb < 4; bb++)
                #pragma unroll
                for (int oo = 0; oo < 8; oo++) {
                    accr[bb][oo] = fmaf(zr[bb], wr[oo], fmaf(-zi[bb], wi[oo], accr[bb][oo]));
                    acci[bb][oo] = fmaf(zr[bb], wi[oo], fmaf( zi[bb], wr[oo], acci[bb][oo]));
                }
        }
    }
    #pragma unroll
    for (int bb = 0; bb < 4; bb++) {
        size_t rowr = ((size_t)(m * 2 + 0) * NB + bt * 64 + b0 + bb) * HID + o0;
        size_t rowi = ((size_t)(m * 2 + 1) * NB + bt * 64 + b0 + bb) * HID + o0;
        #pragma unroll
        for (int oo = 0; oo < 8; oo++) {
            g_of2[rowr + oo] = accr[bb][oo];
            g_of2[rowi + oo] = acci[bb][oo];
        }
    }
}

// ---------------- K_layer2: synth + gelu + mean (quad symmetry, smem tables) ----------
__global__ __launch_bounds__(256, 2) void k_layer2(float* __restrict__ out) {
    __shared__ __align__(16) float smC[64 * 32];
    __shared__ __align__(16) float smS[64 * 32];
    int b = blockIdx.x;
    int t = threadIdx.x;
    int lane = t & 31, w = t >> 5, hh = lane >> 4;
    int o = w * 16 + (lane & 15);
    float sgn  = hh ? -1.0f : 1.0f;
    float msgn = -sgn;

    float br[16], bi[16];
    #pragma unroll
    for (int j = 0; j < 16; j++) {
        int m = hh * 16 + j;
        float orr = __ldg(&g_of2[((size_t)(m * 2 + 0) * NB + b) * HID + o]);
        float oii = __ldg(&g_of2[((size_t)(m * 2 + 1) * NB + b) * HID + o]);
        float km = (m == 0) ? (1.0f / SLEN) : (2.0f / SLEN);
        br[j] = km * orr;
        bi[j] = (m == 0) ? 0.0f : -km * oii;
    }

    const float4* tC = reinterpret_cast<const float4*>(g_tabC);
    const float4* tS = reinterpret_cast<const float4*>(g_tabS);
    int base = hh * 4;
    float acc = 0.0f;                          // per-thread partial (own points only)

    {   // s=0 (t0 adds) and s=512 (t1 adds)
        float c0[16], c5[16];
        #pragma unroll
        for (int q = 0; q < 4; q++) {
            float4 a = __ldg(&tC[0 * 8 + base + q]);
            float4 c = __ldg(&tC[512 * 8 + base + q]);
            c0[4*q+0]=a.x; c0[4*q+1]=a.y; c0[4*q+2]=a.z; c0[4*q+3]=a.w;
            c5[4*q+0]=c.x; c5[4*q+1]=c.y; c5[4*q+2]=c.z; c5[4*q+3]=c.w;
        }
        float u0 = 0.0f, u5 = 0.0f;
        #pragma unroll
        for (int j = 0; j < 16; j++) {
            u0 = fmaf(br[j], c0[j], u0);
            u5 = fmaf(br[j], c5[j], u5);
        }
        u0 += __shfl_xor_sync(0xffffffffu, u0, 16);
        u5 += __shfl_xor_sync(0xffffffffu, u5, 16);
        acc += gelu_fast(hh ? u5 : u0);
    }

    {   // s=256 (t0 adds) / s=768 (t1 adds)
        float c[16], sn[16];
        #pragma unroll
        for (int q = 0; q < 4; q++) {
            float4 a = __ldg(&tC[256 * 8 + base + q]);
            float4 s = __ldg(&tS[256 * 8 + base + q]);
            c [4*q+0]=a.x; c [4*q+1]=a.y; c [4*q+2]=a.z; c [4*q+3]=a.w;
            sn[4*q+0]=s.x; sn[4*q+1]=s.y; sn[4*q+2]=s.z; sn[4*q+3]=s.w;
        }
        float u = 0.0f, v = 0.0f;
        #pragma unroll
        for (int j = 0; j < 16; j++) {
            u = fmaf(br[j], c[j], u);
            v = fmaf(bi[j], sn[j], v);
        }
        float ya = u + v, yb = u - v;
        ya += __shfl_xor_sync(0xffffffffu, ya, 16);
        yb += __shfl_xor_sync(0xffffffffu, yb, 16);
        acc += gelu_fast(hh ? yb : ya);
    }

    // pack
    u64 br2[8], bi2[8];
    #pragma unroll
    for (int k = 0; k < 8; k++) {
        br2[k] = pk2(br[2*k], br[2*k+1]);
        bi2[k] = pk2(bi[2*k], bi[2*k+1]);
    }

    unsigned smC_a = s2u(smC) + hh * 64;
    unsigned smS_a = s2u(smS) + hh * 64;

    for (int pb = 0; pb < 256; pb += 64) {
        __syncthreads();
        for (int j = t; j < 512; j += 256) {
            int row = j >> 3, col = j & 7;
            reinterpret_cast<float4*>(smC)[j] = __ldg(&tC[(pb + row) * 8 + col]);
            reinterpret_cast<float4*>(smS)[j] = __ldg(&tS[(pb + row) * 8 + col]);
        }
        __syncthreads();
        int p0 = (pb == 0) ? 1 : pb;
        for (int p = p0; p < pb + 64; p++) {
            unsigned off = (unsigned)(p - pb) * 128;
            u64 c2[8], s2[8];
            lds2u64(c2[0], c2[1], smC_a + off);
            lds2u64(c2[2], c2[3], smC_a + off + 16);
            lds2u64(c2[4], c2[5], smC_a + off + 32);
            lds2u64(c2[6], c2[7], smC_a + off + 48);
            lds2u64(s2[0], s2[1], smS_a + off);
            lds2u64(s2[2], s2[3], smS_a + off + 16);
            lds2u64(s2[4], s2[5], smS_a + off + 32);
            lds2u64(s2[6], s2[7], smS_a + off + 48);

            u64 u2a = 0ull, u2b = 0ull, v2a = 0ull, v2b = 0ull;
            #pragma unroll
            for (int k = 0; k < 4; k++) {
                u2a = f2fma(br2[k],     c2[k],     u2a);
                u2b = f2fma(br2[k + 4], c2[k + 4], u2b);
                v2a = f2fma(bi2[k],     s2[k],     v2a);
                v2b = f2fma(bi2[k + 4], s2[k + 4], v2b);
            }
            float ue, uo, ve, vo;
            un2(f2add(u2a, u2b), ue, uo);
            un2(f2add(v2a, v2b), ve, vo);
            float keepU = fmaf(sgn,  uo, ue);
            float sendU = fmaf(msgn, uo, ue);
            float keepV = fmaf(sgn,  vo, ve);
            float sendV = fmaf(msgn, vo, ve);
            float U = keepU + __shfl_xor_sync(0xffffffffu, sendU, 16);
            float V = keepV + __shfl_xor_sync(0xffffffffu, sendV, 16);
            float za, zb;
            gelu2(U + V, U - V, za, zb);
            acc += za + zb;
        }
    }

    acc += __shfl_xor_sync(0xffffffffu, acc, 16);
    if (hh == 0) out[(size_t)b * HID + o] = acc * (1.0f / SLEN);
}

// ---------------- launch ----------------
extern "C" void kernel_launch(void* const* d_in, const int* in_sizes, int n_in,
                              void* d_out, int out_size) {
    const float* hin = nullptr;
    const float* w1p[2] = {nullptr, nullptr};
    const float* w2p[2] = {nullptr, nullptr};
    int n1 = 0, n2 = 0;
    for (int i = 0; i < n_in; i++) {
        int sz = in_sizes[i];
        const float* p = (const float*)d_in[i];
        if (sz == NB * SLEN) hin = p;
        else if (sz == HID * NM) { if (n1 < 2) w1p[n1++] = p; }
        else if (sz == HID * HID * NM) { if (n2 < 2) w2p[n2++] = p; }
    }
    float* out = (float*)d_out;

    k_tab<<<(SLEN * NM + 255) / 256, 256>>>();
    k_w<<<(NM * HID * HID + 255) / 256, 256>>>(w1p[0], w1p[1], w2p[0], w2p[1]);
    k_layer1<<<NB, 256>>>(hin);
    dim3 g3(NM, 16);
    k_mix<<<g3, 256>>>();
    k_layer2<<<NB, 256>>>(out);
}

// round 11
// speedup vs baseline: 1.5803x; 1.0453x over previous
#include <cuda_runtime.h>
#include <math.h>

#define SLEN 1024
#define NM   32
#define HID  128
#define NB   1024

typedef unsigned long long u64;

// ---------------- scratch (static device memory; no allocation) ----------------
__device__ float g_tabC[SLEN*NM];          // cos(2*pi*m*s/S), [s][m]
__device__ float g_tabS[SLEN*NM];          // sin(2*pi*m*s/S), [s][m]
__device__ float g_w1tr[NM*HID];           // [m][ch]
__device__ float g_w1ti[NM*HID];
__device__ u64   g_w2p[NM*HID*HID];        // [m][i][o] packed (wr, wi)
__device__ u64   g_w2n[NM*HID*HID];        // [m][i][o] packed (-wi, wr)
__device__ float g_Zf [2*NM*NB*HID];       // [(m*2+ri)][b][ch]
__device__ float g_of2[2*NM*NB*HID];       // [(m*2+ri)][b][o]

// ---------------- packed f32x2 helpers ----------------
__device__ __forceinline__ u64 pk2(float lo, float hi) {
    u64 r; asm("mov.b64 %0, {%1, %2};" : "=l"(r) : "f"(lo), "f"(hi)); return r;
}
__device__ __forceinline__ void un2(u64 v, float& lo, float& hi) {
    asm("mov.b64 {%0, %1}, %2;" : "=f"(lo), "=f"(hi) : "l"(v));
}
__device__ __forceinline__ u64 f2fma(u64 a, u64 b, u64 c) {
    u64 d; asm("fma.rn.f32x2 %0, %1, %2, %3;" : "=l"(d) : "l"(a), "l"(b), "l"(c)); return d;
}
__device__ __forceinline__ u64 f2mul(u64 a, u64 b) {
    u64 d; asm("mul.rn.f32x2 %0, %1, %2;" : "=l"(d) : "l"(a), "l"(b)); return d;
}
__device__ __forceinline__ u64 f2add(u64 a, u64 b) {
    u64 d; asm("add.rn.f32x2 %0, %1, %2;" : "=l"(d) : "l"(a), "l"(b)); return d;
}
__device__ __forceinline__ unsigned s2u(const void* p) {
    return (unsigned)__cvta_generic_to_shared(p);
}
// 16B shared load -> two packed f32x2 operands
__device__ __forceinline__ void lds2u64(u64& a, u64& b, unsigned addr) {
    asm volatile("ld.shared.v2.u64 {%0, %1}, [%2];" : "=l"(a), "=l"(b) : "r"(addr));
}
#define PKC(x) pk2((x), (x))

// High-accuracy GELU (A&S 7.1.26 erf), used on special points only.
__device__ __forceinline__ float gelu_fast(float x) {
    float q    = fabsf(x) * 0.70710678118654752f;
    float t    = __fdividef(1.0f, fmaf(0.3275911f, q, 1.0f));
    float poly = fmaf(fmaf(fmaf(fmaf(1.061405429f, t, -1.453152027f),
                               t, 1.421413741f),
                          t, -0.284496736f),
                      t, 0.254829592f) * t;
    float er   = 1.0f - poly * __expf(-q * q);
    float phi  = fmaf(copysignf(er, x), 0.5f, 0.5f);
    return x * phi;
}

// Two-point GELU, hot path: A&S 7.1.25 3-term erf (abs err 2.5e-5), packed poly.
__device__ __forceinline__ void gelu2(float xa, float xb, float& za, float& zb) {
    float qa = fabsf(xa) * 0.70710678118654752f;
    float qb = fabsf(xb) * 0.70710678118654752f;
    float ta = __fdividef(1.0f, fmaf(0.47047f, qa, 1.0f));
    float tb = __fdividef(1.0f, fmaf(0.47047f, qb, 1.0f));
    u64 t2 = pk2(ta, tb);
    u64 p  = f2fma(t2, PKC(0.7478556f), PKC(-0.0958798f));
    p = f2fma(p, t2, PKC(0.3480242f));
    p = f2mul(p, t2);
    float ea = __expf(-qa * qa), eb = __expf(-qb * qb);
    float pa, pb; un2(p, pa, pb);
    float era = fmaf(-pa, ea, 1.0f), erb = fmaf(-pb, eb, 1.0f);
    za = xa * fmaf(copysignf(era, xa), 0.5f, 0.5f);
    zb = xb * fmaf(copysignf(erb, xb), 0.5f, 0.5f);
}

// ---------------- K_tab: exact trig tables ----------------
__global__ void k_tab() {
    int idx = blockIdx.x * blockDim.x + threadIdx.x;
    if (idx >= SLEN * NM) return;
    int s = idx >> 5, m = idx & 31;
    int k = (s * m) & (SLEN - 1);
    float x = (float)k * (1.0f / 512.0f);
    float sv, cv;
    sincospif(x, &sv, &cv);
    g_tabC[idx] = cv;
    g_tabS[idx] = sv;
}

// ---------------- K_w: weight transposes + complex packing ----------------
__global__ void k_w(const float* __restrict__ w1r, const float* __restrict__ w1i,
                    const float* __restrict__ w2r, const float* __restrict__ w2i) {
    int tid = blockIdx.x * blockDim.x + threadIdx.x;
    if (tid < NM * HID) {
        int ch = tid >> 5, m = tid & 31;
        g_w1tr[m * HID + ch] = w1r[tid];
        g_w1ti[m * HID + ch] = w1i[tid];
    }
    if (tid < NM * HID * HID) {
        int m = tid & 31; int io = tid >> 5;
        int i = io >> 7;  int o = io & 127;
        float wr = w2r[tid], wi = w2i[tid];
        size_t dst = ((size_t)m * HID + i) * HID + o;
        g_w2p[dst] = pk2(wr, wi);
        g_w2n[dst] = pk2(-wi, wr);
    }
}

// ---------------- K_layer1: DFT(h) -> mix w1 -> synth+gelu+analyze (smem tables) -------
__global__ __launch_bounds__(256, 2) void k_layer1(const float* __restrict__ hin) {
    __shared__ float h_sm[SLEN];
    __shared__ float red[64 * 4];
    __shared__ float Hf[64];                   // [0:32) real, [32:64) imag
    __shared__ __align__(16) float smC[64 * 32];   // 64-row chunk of cos table
    __shared__ __align__(16) float smS[64 * 32];   // 64-row chunk of sin table
    int b = blockIdx.x;
    int t = threadIdx.x;

    // stage h row
    {
        const float4* src = reinterpret_cast<const float4*>(hin + (size_t)b * SLEN);
        float4* dst = reinterpret_cast<float4*>(h_sm);
        for (int j = t; j < SLEN / 4; j += 256) dst[j] = src[j];
    }
    __syncthreads();

    // forward DFT of h: Hfr[m] = sum h*cos, Hfi[m] = -sum h*sin
    {
        int out = t & 63, seg = t >> 6;
        int m = out & 31; int isI = out >> 5;
        const float* tab = isI ? g_tabS : g_tabC;
        float acc = 0.0f;
        int s0 = seg * 256;
        #pragma unroll 8
        for (int j = 0; j < 256; j++) {
            int s = s0 + j;
            acc = fmaf(h_sm[s], __ldg(&tab[s * NM + m]), acc);
        }
        red[out * 4 + seg] = acc;
    }
    __syncthreads();
    if (t < 64) {
        float v = red[t * 4] + red[t * 4 + 1] + red[t * 4 + 2] + red[t * 4 + 3];
        Hf[t] = (t >= 32) ? -v : v;
    }
    __syncthreads();

    int lane = t & 31;
    int w    = t >> 5;
    int hh   = lane >> 4;                      // mode-half / point-group owner
    int ch   = w * 16 + (lane & 15);
    float sgn  = hh ? -1.0f : 1.0f;
    float msgn = -sgn;

    // synthesis coefficients: y(s) = sum ar[m]*cos + ai[m]*sin
    float ar[16], ai[16], zfr[16], zfi[16];
    #pragma unroll
    for (int j = 0; j < 16; j++) {
        int m = hh * 16 + j;
        float hr = Hf[m], hi = Hf[32 + m];
        float a1 = __ldg(&g_w1tr[m * HID + ch]);
        float b1 = __ldg(&g_w1ti[m * HID + ch]);
        float km = (m == 0) ? (1.0f / SLEN) : (2.0f / SLEN);
        ar[j] = km * (hr * a1 - hi * b1);
        float oi = km * (hr * b1 + hi * a1);
        ai[j] = (m == 0) ? 0.0f : -oi;         // DC imag dropped by irfft
        zfr[j] = 0.0f; zfi[j] = 0.0f;
    }

    const float4* tC = reinterpret_cast<const float4*>(g_tabC);
    const float4* tS = reinterpret_cast<const float4*>(g_tabS);
    int base = hh * 4;                         // float4 offset inside 8-float4 row

    // special points s=0 and s=512 (sin == 0 there)
    {
        float c0[16], c5[16];
        #pragma unroll
        for (int q = 0; q < 4; q++) {
            float4 a = __ldg(&tC[0 * 8 + base + q]);
            float4 c = __ldg(&tC[512 * 8 + base + q]);
            c0[4*q+0]=a.x; c0[4*q+1]=a.y; c0[4*q+2]=a.z; c0[4*q+3]=a.w;
            c5[4*q+0]=c.x; c5[4*q+1]=c.y; c5[4*q+2]=c.z; c5[4*q+3]=c.w;
        }
        float u0 = 0.0f, u5 = 0.0f;
        #pragma unroll
        for (int j = 0; j < 16; j++) {
            u0 = fmaf(ar[j], c0[j], u0);
            u5 = fmaf(ar[j], c5[j], u5);
        }
        u0 += __shfl_xor_sync(0xffffffffu, u0, 16);
        u5 += __shfl_xor_sync(0xffffffffu, u5, 16);
        float z0 = gelu_fast(u0), z5 = gelu_fast(u5);
        #pragma unroll
        for (int j = 0; j < 16; j++)
            zfr[j] = fmaf(z0, c0[j], fmaf(z5, c5[j], zfr[j]));
    }

    // special pair s=256 / s=768 (half-wave symmetry)
    {
        float c[16], sn[16];
        #pragma unroll
        for (int q = 0; q < 4; q++) {
            float4 a = __ldg(&tC[256 * 8 + base + q]);
            float4 s = __ldg(&tS[256 * 8 + base + q]);
            c [4*q+0]=a.x; c [4*q+1]=a.y; c [4*q+2]=a.z; c [4*q+3]=a.w;
            sn[4*q+0]=s.x; sn[4*q+1]=s.y; sn[4*q+2]=s.z; sn[4*q+3]=s.w;
        }
        float u = 0.0f, v = 0.0f;
        #pragma unroll
        for (int j = 0; j < 16; j++) {
            u = fmaf(ar[j], c[j], u);
            v = fmaf(ai[j], sn[j], v);
        }
        float ya = u + v, yb = u - v;          // y(256), y(768)
        ya += __shfl_xor_sync(0xffffffffu, ya, 16);
        yb += __shfl_xor_sync(0xffffffffu, yb, 16);
        float ymine = hh ? yb : ya;
        float zmine = gelu_fast(ymine);
        float zoth  = __shfl_xor_sync(0xffffffffu, zmine, 16);
        float z0 = hh ? zoth : zmine;          // z(256)
        float z1 = hh ? zmine : zoth;          // z(768)
        float zp = z0 + z1, zd = z1 - z0;
        #pragma unroll
        for (int j = 0; j < 16; j++) {
            zfr[j] = fmaf(zp, c[j],  zfr[j]);
            zfi[j] = fmaf(zd, sn[j], zfi[j]);
        }
    }

    // pack coefficients and accumulators into f32x2 pairs (even/odd mode lanes)
    u64 ar2[8], ai2[8], zfr2[8], zfi2[8];
    #pragma unroll
    for (int k = 0; k < 8; k++) {
        ar2[k]  = pk2(ar[2*k],  ar[2*k+1]);
        ai2[k]  = pk2(ai[2*k],  ai[2*k+1]);
        zfr2[k] = pk2(zfr[2*k], zfr[2*k+1]);
        zfi2[k] = pk2(zfi[2*k], zfi[2*k+1]);
    }

    unsigned smC_a = s2u(smC) + hh * 64;       // hh selects 16-float half of row
    unsigned smS_a = s2u(smS) + hh * 64;

    // quad points {p, 1024-p, 512+p, 512-p}, p = 1..255, smem-staged tables
    for (int pb = 0; pb < 256; pb += 64) {
        __syncthreads();
        // cooperative stage: rows pb..pb+63 of both tables (512 float4 each)
        for (int j = t; j < 512; j += 256) {
            int row = j >> 3, col = j & 7;
            reinterpret_cast<float4*>(smC)[j] = __ldg(&tC[(pb + row) * 8 + col]);
            reinterpret_cast<float4*>(smS)[j] = __ldg(&tS[(pb + row) * 8 + col]);
        }
        __syncthreads();
        int p0 = (pb == 0) ? 1 : pb;
        for (int p = p0; p < pb + 64; p++) {
            unsigned off = (unsigned)(p - pb) * 128;   // 32 floats/row
            u64 c2[8], s2[8];
            lds2u64(c2[0], c2[1], smC_a + off);
            lds2u64(c2[2], c2[3], smC_a + off + 16);
            lds2u64(c2[4], c2[5], smC_a + off + 32);
            lds2u64(c2[6], c2[7], smC_a + off + 48);
            lds2u64(s2[0], s2[1], smS_a + off);
            lds2u64(s2[2], s2[3], smS_a + off + 16);
            lds2u64(s2[4], s2[5], smS_a + off + 32);
            lds2u64(s2[6], s2[7], smS_a + off + 48);

            // split accumulation chains (2x4 deep) for latency
            u64 u2a = 0ull, u2b = 0ull, v2a = 0ull, v2b = 0ull;
            #pragma unroll
            for (int k = 0; k < 4; k++) {
                u2a = f2fma(ar2[k],     c2[k],     u2a);
                u2b = f2fma(ar2[k + 4], c2[k + 4], u2b);
                v2a = f2fma(ai2[k],     s2[k],     v2a);
                v2b = f2fma(ai2[k + 4], s2[k + 4], v2b);
            }
            float ue, uo, ve, vo;
            un2(f2add(u2a, u2b), ue, uo);
            un2(f2add(v2a, v2b), ve, vo);
            // select-free parity folds: keep = my points' combo, send = partner's
            float keepU = fmaf(sgn,  uo, ue);
            float sendU = fmaf(msgn, uo, ue);
            float keepV = fmaf(sgn,  vo, ve);
            float sendV = fmaf(msgn, vo, ve);
            float U = keepU + __shfl_xor_sync(0xffffffffu, sendU, 16);
            float V = keepV + __shfl_xor_sync(0xffffffffu, sendV, 16);
            float za, zb;
            gelu2(U + V, U - V, za, zb);       // t0: z(p), z(1024-p); t1: z(512+p), z(512-p)
            float sP = za + zb;                // pair-sum (cos side)
            float sM = zb - za;                // pair-diff (sin side)
            float oP = __shfl_xor_sync(0xffffffffu, sP, 16);
            float oM = __shfl_xor_sync(0xffffffffu, sM, 16);
            // cos weights: even = sP+oP, odd = sgn*(sP-oP); sin likewise
            u64 r2 = pk2(sP + oP, sgn * (sP - oP));
            u64 i2 = pk2(sM + oM, sgn * (sM - oM));
            #pragma unroll
            for (int k = 0; k < 8; k++) {
                zfr2[k] = f2fma(r2, c2[k], zfr2[k]);
                zfi2[k] = f2fma(i2, s2[k], zfi2[k]);
            }
        }
    }

    #pragma unroll
    for (int k = 0; k < 8; k++) {
        float r0, r1, i0, i1;
        un2(zfr2[k], r0, r1);
        un2(zfi2[k], i0, i1);
        int m0 = hh * 16 + 2 * k;
        g_Zf[((size_t)((m0    ) * 2 + 0) * NB + b) * HID + ch] = r0;
        g_Zf[((size_t)((m0    ) * 2 + 1) * NB + b) * HID + ch] = i0;
        g_Zf[((size_t)((m0 + 1) * 2 + 0) * NB + b) * HID + ch] = r1;
        g_Zf[((size_t)((m0 + 1) * 2 + 1) * NB + b) * HID + ch] = i1;
    }
}

// ---------------- K_mix: per-mode complex GEMM, packed FFMA2 (conflict-free) ----------
// Thread outputs o = o_g + 16k (strided): weight LDS.64 across 16 lanes = one 128B line.
__global__ __launch_bounds__(256, 2) void k_mix() {
    int m  = blockIdx.x;
    int bt = blockIdx.y;
    __shared__ float Zr[64 * 17], Zi[64 * 17];
    __shared__ __align__(16) u64 Wp[16 * 128];
    __shared__ __align__(16) u64 Wn[16 * 128];
    int t = threadIdx.x;
    int bo_g = t >> 4, o_g = t & 15;
    int b0 = bo_g * 4;

    u64 acc2[4][8];
    #pragma unroll
    for (int x = 0; x < 4; x++)
        #pragma unroll
        for (int y = 0; y < 8; y++) acc2[x][y] = 0ull;

    const float* Zsr = g_Zf + ((size_t)(m * 2 + 0) * NB + bt * 64) * HID;
    const float* Zsi = g_Zf + ((size_t)(m * 2 + 1) * NB + bt * 64) * HID;

    for (int i0 = 0; i0 < HID; i0 += 16) {
        __syncthreads();
        for (int idx = t; idx < 64 * 16; idx += 256) {
            int bb = idx >> 4, ic = idx & 15;
            Zr[bb * 17 + ic] = Zsr[bb * HID + i0 + ic];
            Zi[bb * 17 + ic] = Zsi[bb * HID + i0 + ic];
        }
        for (int idx = t; idx < 16 * 128; idx += 256) {
            int ic = idx >> 7, o = idx & 127;
            size_t src = ((size_t)m * HID + i0 + ic) * HID + o;
            Wp[idx] = g_w2p[src];
            Wn[idx] = g_w2n[src];
        }
        __syncthreads();
        #pragma unroll 4
        for (int ic = 0; ic < 16; ic++) {
            u64 zrr[4], zii[4];
            #pragma unroll
            for (int bb = 0; bb < 4; bb++) {
                float zr = Zr[(b0 + bb) * 17 + ic];
                float zi = Zi[(b0 + bb) * 17 + ic];
                zrr[bb] = pk2(zr, zr);
                zii[bb] = pk2(zi, zi);
            }
            u64 wp[8], wn[8];
            #pragma unroll
            for (int k = 0; k < 8; k++) {
                wp[k] = Wp[ic * 128 + o_g + 16 * k];
                wn[k] = Wn[ic * 128 + o_g + 16 * k];
            }
            #pragma unroll
            for (int bb = 0; bb < 4; bb++)
                #pragma unroll
                for (int k = 0; k < 8; k++) {
                    acc2[bb][k] = f2fma(zrr[bb], wp[k], acc2[bb][k]);
                    acc2[bb][k] = f2fma(zii[bb], wn[k], acc2[bb][k]);
                }
        }
    }
    #pragma unroll
    for (int bb = 0; bb < 4; bb++) {
        size_t rowr = ((size_t)(m * 2 + 0) * NB + bt * 64 + b0 + bb) * HID;
        size_t rowi = ((size_t)(m * 2 + 1) * NB + bt * 64 + b0 + bb) * HID;
        #pragma unroll
        for (int k = 0; k < 8; k++) {
            float re, im;
            un2(acc2[bb][k], re, im);
            int o = o_g + 16 * k;
            g_of2[rowr + o] = re;
            g_of2[rowi + o] = im;
        }
    }
}

// ---------------- K_layer2: synth + gelu + mean (quad symmetry, smem tables, occ 3) ----
__global__ __launch_bounds__(256, 3) void k_layer2(float* __restrict__ out) {
    __shared__ __align__(16) float smC[64 * 32];
    __shared__ __align__(16) float smS[64 * 32];
    int b = blockIdx.x;
    int t = threadIdx.x;
    int lane = t & 31, w = t >> 5, hh = lane >> 4;
    int o = w * 16 + (lane & 15);
    float sgn  = hh ? -1.0f : 1.0f;
    float msgn = -sgn;

    float br[16], bi[16];
    #pragma unroll
    for (int j = 0; j < 16; j++) {
        int m = hh * 16 + j;
        float orr = __ldg(&g_of2[((size_t)(m * 2 + 0) * NB + b) * HID + o]);
        float oii = __ldg(&g_of2[((size_t)(m * 2 + 1) * NB + b) * HID + o]);
        float km = (m == 0) ? (1.0f / SLEN) : (2.0f / SLEN);
        br[j] = km * orr;
        bi[j] = (m == 0) ? 0.0f : -km * oii;
    }

    const float4* tC = reinterpret_cast<const float4*>(g_tabC);
    const float4* tS = reinterpret_cast<const float4*>(g_tabS);
    int base = hh * 4;
    float acc = 0.0f;                          // per-thread partial (own points only)

    {   // s=0 (t0 adds) and s=512 (t1 adds)
        float c0[16], c5[16];
        #pragma unroll
        for (int q = 0; q < 4; q++) {
            float4 a = __ldg(&tC[0 * 8 + base + q]);
            float4 c = __ldg(&tC[512 * 8 + base + q]);
            c0[4*q+0]=a.x; c0[4*q+1]=a.y; c0[4*q+2]=a.z; c0[4*q+3]=a.w;
            c5[4*q+0]=c.x; c5[4*q+1]=c.y; c5[4*q+2]=c.z; c5[4*q+3]=c.w;
        }
        float u0 = 0.0f, u5 = 0.0f;
        #pragma unroll
        for (int j = 0; j < 16; j++) {
            u0 = fmaf(br[j], c0[j], u0);
            u5 = fmaf(br[j], c5[j], u5);
        }
        u0 += __shfl_xor_sync(0xffffffffu, u0, 16);
        u5 += __shfl_xor_sync(0xffffffffu, u5, 16);
        acc += gelu_fast(hh ? u5 : u0);
    }

    {   // s=256 (t0 adds) / s=768 (t1 adds)
        float c[16], sn[16];
        #pragma unroll
        for (int q = 0; q < 4; q++) {
            float4 a = __ldg(&tC[256 * 8 + base + q]);
            float4 s = __ldg(&tS[256 * 8 + base + q]);
            c [4*q+0]=a.x; c [4*q+1]=a.y; c [4*q+2]=a.z; c [4*q+3]=a.w;
            sn[4*q+0]=s.x; sn[4*q+1]=s.y; sn[4*q+2]=s.z; sn[4*q+3]=s.w;
        }
        float u = 0.0f, v = 0.0f;
        #pragma unroll
        for (int j = 0; j < 16; j++) {
            u = fmaf(br[j], c[j], u);
            v = fmaf(bi[j], sn[j], v);
        }
        float ya = u + v, yb = u - v;
        ya += __shfl_xor_sync(0xffffffffu, ya, 16);
        yb += __shfl_xor_sync(0xffffffffu, yb, 16);
        acc += gelu_fast(hh ? yb : ya);
    }

    // pack
    u64 br2[8], bi2[8];
    #pragma unroll
    for (int k = 0; k < 8; k++) {
        br2[k] = pk2(br[2*k], br[2*k+1]);
        bi2[k] = pk2(bi[2*k], bi[2*k+1]);
    }

    unsigned smC_a = s2u(smC) + hh * 64;
    unsigned smS_a = s2u(smS) + hh * 64;

    for (int pb = 0; pb < 256; pb += 64) {
        __syncthreads();
        for (int j = t; j < 512; j += 256) {
            int row = j >> 3, col = j & 7;
            reinterpret_cast<float4*>(smC)[j] = __ldg(&tC[(pb + row) * 8 + col]);
            reinterpret_cast<float4*>(smS)[j] = __ldg(&tS[(pb + row) * 8 + col]);
        }
        __syncthreads();
        int p0 = (pb == 0) ? 1 : pb;
        for (int p = p0; p < pb + 64; p++) {
            unsigned off = (unsigned)(p - pb) * 128;
            u64 c2[8], s2[8];
            lds2u64(c2[0], c2[1], smC_a + off);
            lds2u64(c2[2], c2[3], smC_a + off + 16);
            lds2u64(c2[4], c2[5], smC_a + off + 32);
            lds2u64(c2[6], c2[7], smC_a + off + 48);
            lds2u64(s2[0], s2[1], smS_a + off);
            lds2u64(s2[2], s2[3], smS_a + off + 16);
            lds2u64(s2[4], s2[5], smS_a + off + 32);
            lds2u64(s2[6], s2[7], smS_a + off + 48);

            u64 u2a = 0ull, u2b = 0ull, v2a = 0ull, v2b = 0ull;
            #pragma unroll
            for (int k = 0; k < 4; k++) {
                u2a = f2fma(br2[k],     c2[k],     u2a);
                u2b = f2fma(br2[k + 4], c2[k + 4], u2b);
                v2a = f2fma(bi2[k],     s2[k],     v2a);
                v2b = f2fma(bi2[k + 4], s2[k + 4], v2b);
            }
            float ue, uo, ve, vo;
            un2(f2add(u2a, u2b), ue, uo);
            un2(f2add(v2a, v2b), ve, vo);
            float keepU = fmaf(sgn,  uo, ue);
            float sendU = fmaf(msgn, uo, ue);
            float keepV = fmaf(sgn,  vo, ve);
            float sendV = fmaf(msgn, vo, ve);
            float U = keepU + __shfl_xor_sync(0xffffffffu, sendU, 16);
            float V = keepV + __shfl_xor_sync(0xffffffffu, sendV, 16);
            float za, zb;
            gelu2(U + V, U - V, za, zb);
            acc += za + zb;
        }
    }

    acc += __shfl_xor_sync(0xffffffffu, acc, 16);
    if (hh == 0) out[(size_t)b * HID + o] = acc * (1.0f / SLEN);
}

// ---------------- launch ----------------
extern "C" void kernel_launch(void* const* d_in, const int* in_sizes, int n_in,
                              void* d_out, int out_size) {
    const float* hin = nullptr;
    const float* w1p[2] = {nullptr, nullptr};
    const float* w2p[2] = {nullptr, nullptr};
    int n1 = 0, n2 = 0;
    for (int i = 0; i < n_in; i++) {
        int sz = in_sizes[i];
        const float* p = (const float*)d_in[i];
        if (sz == NB * SLEN) hin = p;
        else if (sz == HID * NM) { if (n1 < 2) w1p[n1++] = p; }
        else if (sz == HID * HID * NM) { if (n2 < 2) w2p[n2++] = p; }
    }
    float* out = (float*)d_out;

    k_tab<<<(SLEN * NM + 255) / 256, 256>>>();
    k_w<<<(NM * HID * HID + 255) / 256, 256>>>(w1p[0], w1p[1], w2p[0], w2p[1]);
    k_layer1<<<NB, 256>>>(hin);
    dim3 g3(NM, 16);
    k_mix<<<g3, 256>>>();
    k_layer2<<<NB, 256>>>(out);
}